// round 12
// baseline (speedup 1.0000x reference)
#include <cuda_runtime.h>
#include <math.h>
#include <stdint.h>

#define B_   2
#define T_   2048
#define HID  1024
#define NH   16
#define HD   64

// ---------------- scratch (device globals; no allocations allowed) ----------
__device__ float g_Q[B_ * NH * T_ * HD];
__device__ float g_K[B_ * NH * T_ * HD];
__device__ float g_V[B_ * NH * T_ * HD];
__device__ float g_att[B_ * T_ * HID];
__device__ float2 g_ctab[T_ * 32];            // cos/sin table [t][d]
__device__ signed char g_gmask[B_ * T_];
__device__ int g_gcnt[B_];
__device__ int g_glist[B_ * T_];

__device__ __forceinline__ uint32_t cvt_tf32(float f) {
    uint32_t r;
    asm("cvt.rna.tf32.f32 %0, %1;" : "=r"(r) : "f"(f));
    return r;
}
__device__ __forceinline__ uint32_t smem_u32(const void* p) {
    uint32_t a;
    asm("{ .reg .u64 t; cvta.to.shared.u64 t, %1; cvt.u32.u64 %0, t; }"
        : "=r"(a) : "l"(p));
    return a;
}
__device__ __forceinline__ void cp_async16(uint32_t saddr, const void* gptr) {
    asm volatile("cp.async.cg.shared.global [%0], [%1], 16;"
                 :: "r"(saddr), "l"(gptr));
}
__device__ __forceinline__ void cp_commit() {
    asm volatile("cp.async.commit_group;" ::: "memory");
}
template<int N>
__device__ __forceinline__ void cp_wait() {
    asm volatile("cp.async.wait_group %0;" :: "n"(N) : "memory");
}

__device__ __forceinline__ void mma_tf32_16n8k8(
    float* c, uint32_t a0, uint32_t a1, uint32_t a2, uint32_t a3,
    uint32_t b0, uint32_t b1)
{
    asm volatile(
        "mma.sync.aligned.m16n8k8.row.col.f32.tf32.tf32.f32 "
        "{%0,%1,%2,%3}, {%4,%5,%6,%7}, {%8,%9}, {%0,%1,%2,%3};"
        : "+f"(c[0]), "+f"(c[1]), "+f"(c[2]), "+f"(c[3])
        : "r"(a0), "r"(a1), "r"(a2), "r"(a3), "r"(b0), "r"(b1));
}

// ---------------- cos/sin table + gcnt init ----------------------------------
__global__ void costab_kernel()
{
    int id = blockIdx.x * blockDim.x + threadIdx.x;   // 65536
    int t = id >> 5, j = id & 31;
    float invf = (float)exp((double)j * (-log(10000.0) / 32.0));
    float ang = (float)t * invf;
    float s, c;
    sincosf(ang, &s, &c);
    g_ctab[id] = make_float2(c, s);
}

__global__ void ginit_kernel()
{
    if (threadIdx.x < B_) g_gcnt[threadIdx.x] = 0;
}

__global__ void gmask_kernel(const int* __restrict__ ids)
{
    int idx = blockIdx.x * blockDim.x + threadIdx.x;
    if (idx >= B_ * T_) return;
    int id = ids[idx];
    bool g = (id >= 0 && id <= 2);
    g_gmask[idx] = g ? 1 : 0;
    if (g) {
        int b = idx / T_;
        int p = atomicAdd(&g_gcnt[b], 1);
        g_glist[b * T_ + p] = idx - b * T_;
    }
}

// ---------------- TF32 GEMM: 128x128 CTA, 4 warps, 64x64/warp, cp.async -----
// MODE 0: C = A @ W^T + bias (row-major C).
// MODE 1: fused qkv epilogue: split into Q/K/V [B,H,T,D], RoPE on Q,K.
// 32 LDS32 per 32 MMAs in the inner loop (1.0 loads/MMA).
#define GSTR 36
#define STAGE_U32 (2 * 128 * GSTR)            // A+B per stage, 9216 floats
#define NSTAGE 3
#define GS_TOTAL (NSTAGE * STAGE_U32 * 4)     // 110592 B

template<int MODE>
__global__ __launch_bounds__(128, 2) void gemm_tf32_mma(
    const float* __restrict__ A, const float* __restrict__ W,
    const float* __restrict__ bias, float* __restrict__ C,
    int N, int K)
{
    extern __shared__ float smf[];
    const uint32_t sb = smem_u32(smf);

    const int tid = threadIdx.x;              // 0..127
    const int lane = tid & 31;
    const int g   = lane >> 2;
    const int tig = lane & 3;
    const int wid = tid >> 5;                 // 0..3
    const int warp_m = wid >> 1;              // 0..1 (64 rows)
    const int warp_n = wid & 1;               // 0..1 (64 cols)
    const int row0 = blockIdx.y * 128;
    const int col0 = blockIdx.x * 128;

    // cp.async mapping: thread tid loads full row tid of A and of B (8 cp16 each)
    const float* Ag = A + (size_t)(row0 + tid) * K;
    const float* Bg = W + (size_t)(col0 + tid) * K;
    const uint32_t a_s0 = sb + (uint32_t)(tid * GSTR) * 4;
    const uint32_t b_s0 = sb + (uint32_t)(128 * GSTR + tid * GSTR) * 4;

    float c[4][8][4];
    #pragma unroll
    for (int mi = 0; mi < 4; mi++)
        #pragma unroll
        for (int ni = 0; ni < 8; ni++)
            #pragma unroll
            for (int r = 0; r < 4; r++) c[mi][ni][r] = 0.f;

    const int nT = K / 32;

    // prologue: stages 0 and 1 in flight
    #pragma unroll
    for (int s = 0; s < 2; s++) {
        uint32_t soff = (uint32_t)(s * STAGE_U32) * 4;
        const float* ag = Ag + s * 32;
        const float* bg = Bg + s * 32;
        #pragma unroll
        for (int j = 0; j < 8; j++) {
            cp_async16(a_s0 + soff + j * 16, ag + j * 4);
            cp_async16(b_s0 + soff + j * 16, bg + j * 4);
        }
        cp_commit();
    }

    for (int kt = 0; kt < nT; kt++) {
        cp_wait<1>();
        __syncthreads();

        if (kt + 2 < nT) {
            uint32_t soff = (uint32_t)(((kt + 2) % NSTAGE) * STAGE_U32) * 4;
            const float* ag = Ag + (kt + 2) * 32;
            const float* bg = Bg + (kt + 2) * 32;
            #pragma unroll
            for (int j = 0; j < 8; j++) {
                cp_async16(a_s0 + soff + j * 16, ag + j * 4);
                cp_async16(b_s0 + soff + j * 16, bg + j * 4);
            }
        }
        cp_commit();

        const float* As_ = smf + (kt % NSTAGE) * STAGE_U32;
        const float* Bs_ = As_ + 128 * GSTR;
        #pragma unroll
        for (int ks = 0; ks < 4; ks++) {
            const int k = ks * 8 + tig;
            uint32_t a[4][4], b[8][2];
            #pragma unroll
            for (int mi = 0; mi < 4; mi++) {
                int r = warp_m * 64 + mi * 16 + g;
                a[mi][0] = cvt_tf32(As_[r * GSTR + k]);
                a[mi][1] = cvt_tf32(As_[(r + 8) * GSTR + k]);
                a[mi][2] = cvt_tf32(As_[r * GSTR + k + 4]);
                a[mi][3] = cvt_tf32(As_[(r + 8) * GSTR + k + 4]);
            }
            #pragma unroll
            for (int ni = 0; ni < 8; ni++) {
                int n = warp_n * 64 + ni * 8 + g;
                b[ni][0] = cvt_tf32(Bs_[n * GSTR + k]);
                b[ni][1] = cvt_tf32(Bs_[n * GSTR + k + 4]);
            }
            #pragma unroll
            for (int mi = 0; mi < 4; mi++)
                #pragma unroll
                for (int ni = 0; ni < 8; ni++)
                    mma_tf32_16n8k8(c[mi][ni], a[mi][0], a[mi][1], a[mi][2], a[mi][3],
                                    b[ni][0], b[ni][1]);
        }
    }

    if (MODE == 0) {
        #pragma unroll
        for (int mi = 0; mi < 4; mi++) {
            const int row = row0 + warp_m * 64 + mi * 16 + g;
            #pragma unroll
            for (int ni = 0; ni < 8; ni++) {
                const int col = col0 + warp_n * 64 + ni * 8 + 2 * tig;
                float2 v0, v1;
                v0.x = c[mi][ni][0] + bias[col];
                v0.y = c[mi][ni][1] + bias[col + 1];
                v1.x = c[mi][ni][2] + bias[col];
                v1.y = c[mi][ni][3] + bias[col + 1];
                *(float2*)(C + (size_t)row * N + col) = v0;
                *(float2*)(C + (size_t)(row + 8) * N + col) = v1;
            }
        }
    } else {
        // blockIdx.x 0..23: sec = bx>>3 (0=Q,1=K,2=V); head = (bx&7)*2 + warp_n
        const int sec  = blockIdx.x >> 3;
        const int head = (blockIdx.x & 7) * 2 + warp_n;
        #pragma unroll
        for (int mi = 0; mi < 4; mi++) {
            const int row = row0 + warp_m * 64 + mi * 16 + g;
            const int bb = row >> 11, tt = row & (T_ - 1);
            if (sec == 2) {
                const float* bi = bias + 2 * HID + head * HD;
                float* dstb = g_V + (((size_t)(bb * NH + head)) * T_ + tt) * HD;
                #pragma unroll
                for (int ni = 0; ni < 8; ni++) {
                    const int dd = ni * 8 + 2 * tig;
                    float b0 = bi[dd], b1 = bi[dd + 1];
                    float2 v0 = { c[mi][ni][0] + b0, c[mi][ni][1] + b1 };
                    float2 v1 = { c[mi][ni][2] + b0, c[mi][ni][3] + b1 };
                    *(float2*)(dstb + dd) = v0;
                    *(float2*)(dstb + 8 * HD + dd) = v1;
                }
            } else {
                float* dstb = (sec ? g_K : g_Q)
                            + (((size_t)(bb * NH + head)) * T_ + tt) * HD;
                const float* bi = bias + sec * HID + head * HD;
                #pragma unroll
                for (int ni = 0; ni < 4; ni++) {
                    const int dd = ni * 8 + 2 * tig;      // 0..30
                    float x1a = c[mi][ni][0]     + bi[dd];
                    float x1b = c[mi][ni][1]     + bi[dd + 1];
                    float x2a = c[mi][ni + 4][0] + bi[dd + 32];
                    float x2b = c[mi][ni + 4][1] + bi[dd + 33];
                    float y1a = c[mi][ni][2]     + bi[dd];
                    float y1b = c[mi][ni][3]     + bi[dd + 1];
                    float y2a = c[mi][ni + 4][2] + bi[dd + 32];
                    float y2b = c[mi][ni + 4][3] + bi[dd + 33];
                    float2 cs0 = g_ctab[tt * 32 + dd];
                    float2 cs1 = g_ctab[tt * 32 + dd + 1];
                    float2 ds0 = g_ctab[(tt + 8) * 32 + dd];
                    float2 ds1 = g_ctab[(tt + 8) * 32 + dd + 1];
                    float2 r0 = { x1a * cs0.x - x2a * cs0.y, x1b * cs1.x - x2b * cs1.y };
                    float2 r1 = { x1a * cs0.y + x2a * cs0.x, x1b * cs1.y + x2b * cs1.x };
                    float2 r2 = { y1a * ds0.x - y2a * ds0.y, y1b * ds1.x - y2b * ds1.y };
                    float2 r3 = { y1a * ds0.y + y2a * ds0.x, y1b * ds1.y + y2b * ds1.x };
                    *(float2*)(dstb + dd) = r0;
                    *(float2*)(dstb + dd + 32) = r1;
                    *(float2*)(dstb + 8 * HD + dd) = r2;
                    *(float2*)(dstb + 8 * HD + dd + 32) = r3;
                }
            }
        }
    }
}

// ---------------- flash attention: single K/V buffer, 2 CTAs/SM (R8) ---------
#define AQ_STR 68
#define AK_STR 68
#define AV_STR 72
#define AP_STR 68
#define AQ_OFF 0
#define AK_OFF (128 * AQ_STR)
#define AV_OFF (AK_OFF + 64 * AK_STR)
#define AP_OFF (AV_OFF + 64 * AV_STR)
#define A_SMEM_U32 (AP_OFF + 128 * AP_STR)
#define A_SMEM_BYTES (A_SMEM_U32 * 4)           // 105472

__global__ __launch_bounds__(256, 2) void attn_mma_kernel()
{
    extern __shared__ uint32_t smu[];
    __shared__ unsigned char gms[64];

    const int b   = blockIdx.z;
    const int h   = blockIdx.y;
    const int q0  = (gridDim.x - 1 - blockIdx.x) * 128;
    const int tid = threadIdx.x;
    const int lane = tid & 31;
    const int wid  = tid >> 5;
    const int g    = lane >> 2;
    const int tig  = lane & 3;

    const size_t head_off = ((size_t)b * NH + h) * T_ * HD;
    const float* Qg = g_Q + head_off;
    const float* Kg = g_K + head_off;
    const float* Vg = g_V + head_off;

    #pragma unroll
    for (int it = 0; it < 8; it++) {
        int i = tid + it * 256;
        int r = i >> 4, seg = (i & 15) << 2;
        float4 v = *(const float4*)(Qg + (size_t)(q0 + r) * HD + seg);
        uint32_t* d = smu + AQ_OFF + r * AQ_STR + seg;
        d[0] = cvt_tf32(v.x * 0.125f); d[1] = cvt_tf32(v.y * 0.125f);
        d[2] = cvt_tf32(v.z * 0.125f); d[3] = cvt_tf32(v.w * 0.125f);
    }

    float o[8][4];
    #pragma unroll
    for (int nt = 0; nt < 8; nt++)
        #pragma unroll
        for (int r = 0; r < 4; r++) o[nt][r] = 0.f;
    float m0 = -1e30f, m1 = -1e30f, l0 = 0.f, l1 = 0.f;

    const int row_l0 = wid * 16 + g;
    const int row_q0 = q0 + row_l0;
    const int row_q1 = row_q0 + 8;
    const int qmin   = q0 + wid * 16;
    const int kend   = q0 + 128;
    const int pr_row = tid >> 4, pr_seg = (tid & 15) << 2;

    float4 pk[4], pv[4];
    #pragma unroll
    for (int it = 0; it < 4; it++) {
        int r = pr_row + it * 16;
        pk[it] = *(const float4*)(Kg + (size_t)r * HD + pr_seg);
        pv[it] = *(const float4*)(Vg + (size_t)r * HD + pr_seg);
    }

    for (int t0 = 0; t0 < kend; t0 += 64) {
        #pragma unroll
        for (int it = 0; it < 4; it++) {
            int r = pr_row + it * 16;
            uint32_t* dk = smu + AK_OFF + r * AK_STR + pr_seg;
            uint32_t* dv = smu + AV_OFF + r * AV_STR + pr_seg;
            dk[0] = cvt_tf32(pk[it].x); dk[1] = cvt_tf32(pk[it].y);
            dk[2] = cvt_tf32(pk[it].z); dk[3] = cvt_tf32(pk[it].w);
            dv[0] = cvt_tf32(pv[it].x); dv[1] = cvt_tf32(pv[it].y);
            dv[2] = cvt_tf32(pv[it].z); dv[3] = cvt_tf32(pv[it].w);
        }
        if (tid < 64) gms[tid] = (unsigned char)g_gmask[b * T_ + t0 + tid];
        __syncthreads();

        if (t0 + 64 < kend) {
            #pragma unroll
            for (int it = 0; it < 4; it++) {
                int r = t0 + 64 + pr_row + it * 16;
                pk[it] = *(const float4*)(Kg + (size_t)r * HD + pr_seg);
                pv[it] = *(const float4*)(Vg + (size_t)r * HD + pr_seg);
            }
        }

        const uint32_t* Kb = smu + AK_OFF;
        const uint32_t* Vb = smu + AV_OFF;

        float s[8][4];
        #pragma unroll
        for (int nt = 0; nt < 8; nt++)
            #pragma unroll
            for (int r = 0; r < 4; r++) s[nt][r] = 0.f;

        #pragma unroll
        for (int ks = 0; ks < 8; ks++) {
            const int kk = ks * 8 + tig;
            uint32_t a0 = smu[AQ_OFF + (row_l0)     * AQ_STR + kk];
            uint32_t a1 = smu[AQ_OFF + (row_l0 + 8) * AQ_STR + kk];
            uint32_t a2 = smu[AQ_OFF + (row_l0)     * AQ_STR + kk + 4];
            uint32_t a3 = smu[AQ_OFF + (row_l0 + 8) * AQ_STR + kk + 4];
            uint32_t bb[8][2];
            #pragma unroll
            for (int nt = 0; nt < 8; nt++) {
                bb[nt][0] = Kb[(nt * 8 + g) * AK_STR + kk];
                bb[nt][1] = Kb[(nt * 8 + g) * AK_STR + kk + 4];
            }
            #pragma unroll
            for (int nt = 0; nt < 8; nt++)
                mma_tf32_16n8k8(s[nt], a0, a1, a2, a3, bb[nt][0], bb[nt][1]);
        }

        const bool need_mask = (t0 + 63 > qmin);
        float rm0 = -1e30f, rm1 = -1e30f;
        #pragma unroll
        for (int nt = 0; nt < 8; nt++) {
            if (need_mask) {
                int kcol = t0 + nt * 8 + 2 * tig;
                bool gm0 = gms[nt * 8 + 2 * tig] != 0;
                bool gm1 = gms[nt * 8 + 2 * tig + 1] != 0;
                if (!(kcol     <= row_q0 || gm0)) s[nt][0] = -1e30f;
                if (!(kcol + 1 <= row_q0 || gm1)) s[nt][1] = -1e30f;
                if (!(kcol     <= row_q1 || gm0)) s[nt][2] = -1e30f;
                if (!(kcol + 1 <= row_q1 || gm1)) s[nt][3] = -1e30f;
            }
            rm0 = fmaxf(rm0, fmaxf(s[nt][0], s[nt][1]));
            rm1 = fmaxf(rm1, fmaxf(s[nt][2], s[nt][3]));
        }
        rm0 = fmaxf(rm0, __shfl_xor_sync(0xffffffffu, rm0, 1));
        rm0 = fmaxf(rm0, __shfl_xor_sync(0xffffffffu, rm0, 2));
        rm1 = fmaxf(rm1, __shfl_xor_sync(0xffffffffu, rm1, 1));
        rm1 = fmaxf(rm1, __shfl_xor_sync(0xffffffffu, rm1, 2));

        float mn0 = fmaxf(m0, rm0), mn1 = fmaxf(m1, rm1);
        float al0 = __expf(m0 - mn0), al1 = __expf(m1 - mn1);
        l0 *= al0; l1 *= al1;
        #pragma unroll
        for (int nt = 0; nt < 8; nt++) {
            o[nt][0] *= al0; o[nt][1] *= al0;
            o[nt][2] *= al1; o[nt][3] *= al1;
        }
        uint32_t* P0 = smu + AP_OFF + (row_l0)     * AP_STR;
        uint32_t* P1 = smu + AP_OFF + (row_l0 + 8) * AP_STR;
        #pragma unroll
        for (int nt = 0; nt < 8; nt++) {
            float p0 = __expf(s[nt][0] - mn0), p1 = __expf(s[nt][1] - mn0);
            float p2 = __expf(s[nt][2] - mn1), p3 = __expf(s[nt][3] - mn1);
            l0 += p0 + p1; l1 += p2 + p3;
            int cc = nt * 8 + 2 * tig;
            P0[cc] = cvt_tf32(p0); P0[cc + 1] = cvt_tf32(p1);
            P1[cc] = cvt_tf32(p2); P1[cc + 1] = cvt_tf32(p3);
        }
        m0 = mn0; m1 = mn1;
        __syncwarp();

        #pragma unroll
        for (int ks = 0; ks < 8; ks++) {
            const int kk = ks * 8 + tig;
            uint32_t a0 = smu[AP_OFF + (row_l0)     * AP_STR + kk];
            uint32_t a1 = smu[AP_OFF + (row_l0 + 8) * AP_STR + kk];
            uint32_t a2 = smu[AP_OFF + (row_l0)     * AP_STR + kk + 4];
            uint32_t a3 = smu[AP_OFF + (row_l0 + 8) * AP_STR + kk + 4];
            uint32_t bb[8][2];
            #pragma unroll
            for (int nt = 0; nt < 8; nt++) {
                bb[nt][0] = Vb[(ks * 8 + tig)     * AV_STR + nt * 8 + g];
                bb[nt][1] = Vb[(ks * 8 + tig + 4) * AV_STR + nt * 8 + g];
            }
            #pragma unroll
            for (int nt = 0; nt < 8; nt++)
                mma_tf32_16n8k8(o[nt], a0, a1, a2, a3, bb[nt][0], bb[nt][1]);
        }
        __syncthreads();
    }

    l0 += __shfl_xor_sync(0xffffffffu, l0, 1);
    l0 += __shfl_xor_sync(0xffffffffu, l0, 2);
    l1 += __shfl_xor_sync(0xffffffffu, l1, 1);
    l1 += __shfl_xor_sync(0xffffffffu, l1, 2);

    const int ng = g_gcnt[b];
    for (int gi = 0; gi < ng; gi++) {
        int k = g_glist[b * T_ + gi];
        if (k < kend) continue;
        const float* Kr = Kg + (size_t)k * HD;
        const float* Vr = Vg + (size_t)k * HD;
        const float* q0p = Qg + (size_t)row_q0 * HD;
        const float* q1p = Qg + (size_t)row_q1 * HD;
        float s0 = 0.f, s1 = 0.f;
        #pragma unroll
        for (int d = 0; d < HD; d++) {
            float kv = __ldg(Kr + d);
            s0 = fmaf(__ldg(q0p + d), kv, s0);
            s1 = fmaf(__ldg(q1p + d), kv, s1);
        }
        s0 *= 0.125f; s1 *= 0.125f;
        float mn0 = fmaxf(m0, s0), mn1 = fmaxf(m1, s1);
        float al0 = __expf(m0 - mn0), al1 = __expf(m1 - mn1);
        float p0 = __expf(s0 - mn0), p1 = __expf(s1 - mn1);
        l0 = l0 * al0 + p0; l1 = l1 * al1 + p1;
        m0 = mn0; m1 = mn1;
        #pragma unroll
        for (int nt = 0; nt < 8; nt++) {
            int cc = nt * 8 + 2 * tig;
            float v0 = __ldg(Vr + cc), v1 = __ldg(Vr + cc + 1);
            o[nt][0] = o[nt][0] * al0 + p0 * v0;
            o[nt][1] = o[nt][1] * al0 + p0 * v1;
            o[nt][2] = o[nt][2] * al1 + p1 * v0;
            o[nt][3] = o[nt][3] * al1 + p1 * v1;
        }
    }

    float i0 = 1.f / l0, i1 = 1.f / l1;
    float* O0 = g_att + ((size_t)(b * T_ + row_q0)) * HID + h * HD;
    float* O1 = g_att + ((size_t)(b * T_ + row_q1)) * HID + h * HD;
    #pragma unroll
    for (int nt = 0; nt < 8; nt++) {
        int cc = nt * 8 + 2 * tig;
        float2 v0 = { o[nt][0] * i0, o[nt][1] * i0 };
        float2 v1 = { o[nt][2] * i1, o[nt][3] * i1 };
        *(float2*)(O0 + cc) = v0;
        *(float2*)(O1 + cc) = v1;
    }
}

// ---------------- launch -----------------------------------------------------
extern "C" void kernel_launch(void* const* d_in, const int* in_sizes, int n_in,
                              void* d_out, int out_size)
{
    (void)in_sizes; (void)n_in; (void)out_size;
    const float* x      = (const float*)d_in[0];
    const int*   ids    = (const int*)d_in[1];
    const float* qkv_w  = (const float*)d_in[2];
    const float* qkv_b  = (const float*)d_in[3];
    const float* out_w  = (const float*)d_in[4];
    const float* out_b  = (const float*)d_in[5];
    float*       out    = (float*)d_out;

    float* p_att = nullptr;
    cudaGetSymbolAddress((void**)&p_att, g_att);

    cudaFuncSetAttribute(gemm_tf32_mma<0>,
                         cudaFuncAttributeMaxDynamicSharedMemorySize, GS_TOTAL);
    cudaFuncSetAttribute(gemm_tf32_mma<1>,
                         cudaFuncAttributeMaxDynamicSharedMemorySize, GS_TOTAL);
    cudaFuncSetAttribute(attn_mma_kernel,
                         cudaFuncAttributeMaxDynamicSharedMemorySize, A_SMEM_BYTES);

    // 1. cos/sin table
    costab_kernel<<<T_ * 32 / 256, 256>>>();
    // 2-3. global-token mask
    ginit_kernel<<<1, 32>>>();
    gmask_kernel<<<(B_ * T_ + 255) / 256, 256>>>(ids);
    // 4. fused qkv GEMM + bias + RoPE + split -> g_Q/g_K/g_V
    gemm_tf32_mma<1><<<dim3(3 * HID / 128, (B_ * T_) / 128), 128, GS_TOTAL>>>(
        x, qkv_w, qkv_b, nullptr, 3 * HID, HID);
    // 5. attention
    attn_mma_kernel<<<dim3(T_ / 128, NH, B_), 256, A_SMEM_BYTES>>>();
    // 6. out = att @ out_w^T + out_b
    gemm_tf32_mma<0><<<dim3(HID / 128, (B_ * T_) / 128), 128, GS_TOTAL>>>(
        p_att, out_w, out_b, out, HID, HID);
}

// round 14
// speedup vs baseline: 1.5815x; 1.5815x over previous
#include <cuda_runtime.h>
#include <cuda_fp16.h>
#include <math.h>
#include <stdint.h>

#define B_   2
#define T_   2048
#define HID  1024
#define NH   16
#define HD   64

// ---------------- scratch (device globals; no allocations allowed) ----------
__device__ __half g_Qh[B_ * NH * T_ * HD];    // RoPE'd, pre-scaled by 1/8
__device__ __half g_Kh[B_ * NH * T_ * HD];
__device__ __half g_Vh[B_ * NH * T_ * HD];
__device__ float g_att[B_ * T_ * HID];
__device__ float2 g_ctab[T_ * 32];
__device__ signed char g_gmask[B_ * T_];
__device__ int g_gcnt[B_];
__device__ int g_glist[B_ * T_];

__device__ __forceinline__ uint32_t packh2(float lo, float hi) {
    __half2 h = __floats2half2_rn(lo, hi);
    return *reinterpret_cast<uint32_t*>(&h);
}

__device__ __forceinline__ void mma_f16(
    float* c, uint32_t a0, uint32_t a1, uint32_t a2, uint32_t a3,
    uint32_t b0, uint32_t b1)
{
    asm volatile(
        "mma.sync.aligned.m16n8k16.row.col.f32.f16.f16.f32 "
        "{%0,%1,%2,%3}, {%4,%5,%6,%7}, {%8,%9}, {%0,%1,%2,%3};"
        : "+f"(c[0]), "+f"(c[1]), "+f"(c[2]), "+f"(c[3])
        : "r"(a0), "r"(a1), "r"(a2), "r"(a3), "r"(b0), "r"(b1));
}

// ---------------- cos/sin table + gcnt init ----------------------------------
__global__ void costab_kernel()
{
    int id = blockIdx.x * blockDim.x + threadIdx.x;
    int t = id >> 5, j = id & 31;
    float invf = (float)exp((double)j * (-log(10000.0) / 32.0));
    float ang = (float)t * invf;
    float s, c;
    sincosf(ang, &s, &c);
    g_ctab[id] = make_float2(c, s);
}

__global__ void ginit_kernel()
{
    if (threadIdx.x < B_) g_gcnt[threadIdx.x] = 0;
}

__global__ void gmask_kernel(const int* __restrict__ ids)
{
    int idx = blockIdx.x * blockDim.x + threadIdx.x;
    if (idx >= B_ * T_) return;
    int id = ids[idx];
    bool g = (id >= 0 && id <= 2);
    g_gmask[idx] = g ? 1 : 0;
    if (g) {
        int b = idx / T_;
        int p = atomicAdd(&g_gcnt[b], 1);
        g_glist[b * T_ + p] = idx - b * T_;
    }
}

// ---------------- FP16 GEMM (R5 shape: 128x128 CTA, 8 warps, 32x64/warp) ----
// MODE 0: C = A @ W^T + bias (fp32 out).
// MODE 1: fused qkv epilogue -> g_Qh/g_Kh/g_Vh (half), RoPE on Q,K; Q *= 1/8.
#define GWS 20                        // u32 words per row (40 halves: 32+8 pad)
#define GBUFW (128 * GWS)             // 2560 words per tile buffer
#define GS_TOTAL (4 * GBUFW * 4)      // 40960 B (A0,A1,B0,B1)

template<int MODE>
__global__ __launch_bounds__(256, 2) void gemm_f16(
    const float* __restrict__ A, const float* __restrict__ W,
    const float* __restrict__ bias, float* __restrict__ C,
    int N, int K)
{
    extern __shared__ uint32_t smw[];
    uint32_t* As = smw;               // 2 buffers of GBUFW
    uint32_t* Bs = smw + 2 * GBUFW;

    const int tid = threadIdx.x;
    const int lane = tid & 31;
    const int g   = lane >> 2;
    const int tig = lane & 3;
    const int wid = tid >> 5;
    const int warp_m = wid & 3;       // 0..3 (32 rows)
    const int warp_n = wid >> 2;      // 0..1 (64 cols)
    const int row0 = blockIdx.y * 128;
    const int col0 = blockIdx.x * 128;

    const int lrow = tid >> 1;        // 0..127
    const int lh   = tid & 1;         // k-half (16 floats each)

    const float* Ag = A + (size_t)(row0 + lrow) * K + lh * 16;
    const float* Bg = W + (size_t)(col0 + lrow) * K + lh * 16;

    float c[2][8][4];
    #pragma unroll
    for (int mi = 0; mi < 2; mi++)
        #pragma unroll
        for (int ni = 0; ni < 8; ni++)
            #pragma unroll
            for (int r = 0; r < 4; r++) c[mi][ni][r] = 0.f;

    const int nT = K / 32;
    uint4 ua[2], ub[2];               // packed-half prefetch (8 regs each)

    // load+convert tile 0
    #pragma unroll
    for (int j = 0; j < 2; j++) {
        float4 v0 = *(const float4*)(Ag + j * 8);
        float4 v1 = *(const float4*)(Ag + j * 8 + 4);
        ua[j] = make_uint4(packh2(v0.x, v0.y), packh2(v0.z, v0.w),
                           packh2(v1.x, v1.y), packh2(v1.z, v1.w));
        float4 w0 = *(const float4*)(Bg + j * 8);
        float4 w1 = *(const float4*)(Bg + j * 8 + 4);
        ub[j] = make_uint4(packh2(w0.x, w0.y), packh2(w0.z, w0.w),
                           packh2(w1.x, w1.y), packh2(w1.z, w1.w));
    }
    {
        uint32_t* as = As + lrow * GWS + lh * 8;
        uint32_t* bs = Bs + lrow * GWS + lh * 8;
        *(uint4*)as = ua[0]; *(uint4*)(as + 4) = ua[1];
        *(uint4*)bs = ub[0]; *(uint4*)(bs + 4) = ub[1];
    }
    __syncthreads();

    for (int kt = 0; kt < nT; kt++) {
        const int buf = kt & 1;
        if (kt + 1 < nT) {
            const float* Ap = Ag + (kt + 1) * 32;
            const float* Bp = Bg + (kt + 1) * 32;
            #pragma unroll
            for (int j = 0; j < 2; j++) {
                float4 v0 = *(const float4*)(Ap + j * 8);
                float4 v1 = *(const float4*)(Ap + j * 8 + 4);
                ua[j] = make_uint4(packh2(v0.x, v0.y), packh2(v0.z, v0.w),
                                   packh2(v1.x, v1.y), packh2(v1.z, v1.w));
                float4 w0 = *(const float4*)(Bp + j * 8);
                float4 w1 = *(const float4*)(Bp + j * 8 + 4);
                ub[j] = make_uint4(packh2(w0.x, w0.y), packh2(w0.z, w0.w),
                                   packh2(w1.x, w1.y), packh2(w1.z, w1.w));
            }
        }

        const uint32_t* Aw = As + buf * GBUFW;
        const uint32_t* Bw = Bs + buf * GBUFW;
        #pragma unroll
        for (int ks2 = 0; ks2 < 2; ks2++) {
            const int kb = ks2 * 8 + tig;
            uint32_t a[2][4], b[8][2];
            #pragma unroll
            for (int mi = 0; mi < 2; mi++) {
                int r = warp_m * 32 + mi * 16 + g;
                a[mi][0] = Aw[r * GWS + kb];
                a[mi][1] = Aw[(r + 8) * GWS + kb];
                a[mi][2] = Aw[r * GWS + kb + 4];
                a[mi][3] = Aw[(r + 8) * GWS + kb + 4];
            }
            #pragma unroll
            for (int ni = 0; ni < 8; ni++) {
                int n = warp_n * 64 + ni * 8 + g;
                b[ni][0] = Bw[n * GWS + kb];
                b[ni][1] = Bw[n * GWS + kb + 4];
            }
            #pragma unroll
            for (int mi = 0; mi < 2; mi++)
                #pragma unroll
                for (int ni = 0; ni < 8; ni++)
                    mma_f16(c[mi][ni], a[mi][0], a[mi][1], a[mi][2], a[mi][3],
                            b[ni][0], b[ni][1]);
        }

        if (kt + 1 < nT) {
            uint32_t* as = As + (buf ^ 1) * GBUFW + lrow * GWS + lh * 8;
            uint32_t* bs = Bs + (buf ^ 1) * GBUFW + lrow * GWS + lh * 8;
            *(uint4*)as = ua[0]; *(uint4*)(as + 4) = ua[1];
            *(uint4*)bs = ub[0]; *(uint4*)(bs + 4) = ub[1];
        }
        __syncthreads();
    }

    if (MODE == 0) {
        #pragma unroll
        for (int mi = 0; mi < 2; mi++) {
            const int row = row0 + warp_m * 32 + mi * 16 + g;
            #pragma unroll
            for (int ni = 0; ni < 8; ni++) {
                const int col = col0 + warp_n * 64 + ni * 8 + 2 * tig;
                float2 v0, v1;
                v0.x = c[mi][ni][0] + bias[col];
                v0.y = c[mi][ni][1] + bias[col + 1];
                v1.x = c[mi][ni][2] + bias[col];
                v1.y = c[mi][ni][3] + bias[col + 1];
                *(float2*)(C + (size_t)row * N + col) = v0;
                *(float2*)(C + (size_t)(row + 8) * N + col) = v1;
            }
        }
    } else {
        // blockIdx.x 0..23: sec = bx>>3 (0=Q,1=K,2=V); head = (bx&7)*2 + warp_n
        const int sec  = blockIdx.x >> 3;
        const int head = (blockIdx.x & 7) * 2 + warp_n;
        #pragma unroll
        for (int mi = 0; mi < 2; mi++) {
            const int row = row0 + warp_m * 32 + mi * 16 + g;
            const int bb = row >> 11, tt = row & (T_ - 1);
            const size_t hb = (((size_t)(bb * NH + head)) * T_ + tt) * HD;
            if (sec == 2) {
                const float* bi = bias + 2 * HID + head * HD;
                uint32_t* d0 = (uint32_t*)(g_Vh + hb);
                uint32_t* d1 = (uint32_t*)(g_Vh + hb + 8 * HD);
                #pragma unroll
                for (int ni = 0; ni < 8; ni++) {
                    const int dd = ni * 8 + 2 * tig;
                    float b0 = bi[dd], b1 = bi[dd + 1];
                    d0[dd >> 1] = packh2(c[mi][ni][0] + b0, c[mi][ni][1] + b1);
                    d1[dd >> 1] = packh2(c[mi][ni][2] + b0, c[mi][ni][3] + b1);
                }
            } else {
                const float scale = (sec == 0) ? 0.125f : 1.0f;
                uint32_t* d0 = (uint32_t*)((sec ? g_Kh : g_Qh) + hb);
                uint32_t* d1 = d0 + 4 * HD;   // +8*HD halves
                const float* bi = bias + sec * HID + head * HD;
                #pragma unroll
                for (int ni = 0; ni < 4; ni++) {
                    const int dd = ni * 8 + 2 * tig;      // 0..30
                    float x1a = c[mi][ni][0]     + bi[dd];
                    float x1b = c[mi][ni][1]     + bi[dd + 1];
                    float x2a = c[mi][ni + 4][0] + bi[dd + 32];
                    float x2b = c[mi][ni + 4][1] + bi[dd + 33];
                    float y1a = c[mi][ni][2]     + bi[dd];
                    float y1b = c[mi][ni][3]     + bi[dd + 1];
                    float y2a = c[mi][ni + 4][2] + bi[dd + 32];
                    float y2b = c[mi][ni + 4][3] + bi[dd + 33];
                    float2 cs0 = g_ctab[tt * 32 + dd];
                    float2 cs1 = g_ctab[tt * 32 + dd + 1];
                    float2 ds0 = g_ctab[(tt + 8) * 32 + dd];
                    float2 ds1 = g_ctab[(tt + 8) * 32 + dd + 1];
                    d0[dd >> 1] =
                        packh2((x1a * cs0.x - x2a * cs0.y) * scale,
                               (x1b * cs1.x - x2b * cs1.y) * scale);
                    d0[(dd >> 1) + 16] =
                        packh2((x1a * cs0.y + x2a * cs0.x) * scale,
                               (x1b * cs1.y + x2b * cs1.x) * scale);
                    d1[dd >> 1] =
                        packh2((y1a * ds0.x - y2a * ds0.y) * scale,
                               (y1b * ds1.x - y2b * ds1.y) * scale);
                    d1[(dd >> 1) + 16] =
                        packh2((y1a * ds0.y + y2a * ds0.x) * scale,
                               (y1b * ds1.y + y2b * ds1.x) * scale);
                }
            }
        }
    }
}

// ---------------- FP16 flash attention ---------------------------------------
// Block = 128 q rows of one (b,h); 8 warps, 16 rows/warp; key tiles of 64.
// Qs/Ks/Ps: [row][64 halves] stride 36 words; Vt: [d][key] transposed.
#define WS 36                           // u32 words per smem row (72 halves)
#define QS_OFF 0
#define KS_OFF (128 * WS)               // 4608
#define VT_OFF (KS_OFF + 64 * WS)       // 6912
#define PS_OFF (VT_OFF + 64 * WS)       // 9216
#define AT_W   (PS_OFF + 128 * WS)      // 13824 words
#define AT_BYTES (AT_W * 4)             // 55296 B

__global__ __launch_bounds__(256, 2) void attn_f16()
{
    extern __shared__ uint32_t smu[];
    __shared__ unsigned char gms[64];

    const int b   = blockIdx.z;
    const int h   = blockIdx.y;
    const int q0  = (gridDim.x - 1 - blockIdx.x) * 128;
    const int tid = threadIdx.x;
    const int lane = tid & 31;
    const int wid  = tid >> 5;
    const int g    = lane >> 2;
    const int tig  = lane & 3;

    const size_t head_off = ((size_t)b * NH + h) * T_ * HD;
    const __half* Qg = g_Qh + head_off;
    const __half* Kg = g_Kh + head_off;
    const __half* Vg = g_Vh + head_off;

    // Q fill: pure copy (pre-scaled, RoPE'd, fp16)
    #pragma unroll
    for (int it = 0; it < 4; it++) {
        int i = tid + it * 256;          // 0..1023 uint4 slots
        int r = i >> 3, sg = i & 7;
        uint4 v = *(const uint4*)(Qg + (size_t)(q0 + r) * HD + sg * 8);
        *(uint4*)(smu + QS_OFF + r * WS + sg * 4) = v;
    }

    float o[8][4];
    #pragma unroll
    for (int nt = 0; nt < 8; nt++)
        #pragma unroll
        for (int r = 0; r < 4; r++) o[nt][r] = 0.f;
    float m0 = -1e30f, m1 = -1e30f, l0 = 0.f, l1 = 0.f;

    const int row_l0 = wid * 16 + g;
    const int row_q0 = q0 + row_l0;
    const int row_q1 = row_q0 + 8;
    const int qmin   = q0 + wid * 16;
    const int kend   = q0 + 128;

    // K prefetch mapping: 2 slots/thread; V: keypair kp, d-group dg
    const int kp = tid & 31, dg = tid >> 5, d0 = dg * 8;
    uint4 pk[2], pva, pvb;
    #pragma unroll
    for (int it = 0; it < 2; it++) {
        int i = tid + it * 256;
        pk[it] = *(const uint4*)(Kg + (size_t)(i >> 3) * HD + (i & 7) * 8);
    }
    pva = *(const uint4*)(Vg + (size_t)(2 * kp) * HD + d0);
    pvb = *(const uint4*)(Vg + (size_t)(2 * kp + 1) * HD + d0);

    for (int t0 = 0; t0 < kend; t0 += 64) {
        // store K tile
        #pragma unroll
        for (int it = 0; it < 2; it++) {
            int i = tid + it * 256;
            *(uint4*)(smu + KS_OFF + (i >> 3) * WS + (i & 7) * 4) = pk[it];
        }
        // store V transposed: Vt[d][key] packed key-pairs
        {
            const ushort* va = (const ushort*)&pva;
            const ushort* vb = (const ushort*)&pvb;
            #pragma unroll
            for (int j = 0; j < 8; j++)
                smu[VT_OFF + (d0 + j) * WS + kp] =
                    (uint32_t)va[j] | ((uint32_t)vb[j] << 16);
        }
        if (tid < 64) gms[tid] = (unsigned char)g_gmask[b * T_ + t0 + tid];
        __syncthreads();

        // prefetch next tile
        if (t0 + 64 < kend) {
            #pragma unroll
            for (int it = 0; it < 2; it++) {
                int i = tid + it * 256;
                pk[it] = *(const uint4*)(Kg + (size_t)(t0 + 64 + (i >> 3)) * HD + (i & 7) * 8);
            }
            pva = *(const uint4*)(Vg + (size_t)(t0 + 64 + 2 * kp) * HD + d0);
            pvb = *(const uint4*)(Vg + (size_t)(t0 + 64 + 2 * kp + 1) * HD + d0);
        }

        // ---- QK^T (4 k16 steps) ----
        float s[8][4];
        #pragma unroll
        for (int nt = 0; nt < 8; nt++)
            #pragma unroll
            for (int r = 0; r < 4; r++) s[nt][r] = 0.f;

        #pragma unroll
        for (int ks = 0; ks < 4; ks++) {
            const int kb = ks * 8 + tig;
            uint32_t a0 = smu[QS_OFF + row_l0 * WS + kb];
            uint32_t a1 = smu[QS_OFF + (row_l0 + 8) * WS + kb];
            uint32_t a2 = smu[QS_OFF + row_l0 * WS + kb + 4];
            uint32_t a3 = smu[QS_OFF + (row_l0 + 8) * WS + kb + 4];
            uint32_t bb[8][2];
            #pragma unroll
            for (int nt = 0; nt < 8; nt++) {
                int n = nt * 8 + g;
                bb[nt][0] = smu[KS_OFF + n * WS + kb];
                bb[nt][1] = smu[KS_OFF + n * WS + kb + 4];
            }
            #pragma unroll
            for (int nt = 0; nt < 8; nt++)
                mma_f16(s[nt], a0, a1, a2, a3, bb[nt][0], bb[nt][1]);
        }

        // ---- mask + online softmax ----
        const bool need_mask = (t0 + 63 > qmin);
        float rm0 = -1e30f, rm1 = -1e30f;
        #pragma unroll
        for (int nt = 0; nt < 8; nt++) {
            if (need_mask) {
                int kcol = t0 + nt * 8 + 2 * tig;
                bool gm0 = gms[nt * 8 + 2 * tig] != 0;
                bool gm1 = gms[nt * 8 + 2 * tig + 1] != 0;
                if (!(kcol     <= row_q0 || gm0)) s[nt][0] = -1e30f;
                if (!(kcol + 1 <= row_q0 || gm1)) s[nt][1] = -1e30f;
                if (!(kcol     <= row_q1 || gm0)) s[nt][2] = -1e30f;
                if (!(kcol + 1 <= row_q1 || gm1)) s[nt][3] = -1e30f;
            }
            rm0 = fmaxf(rm0, fmaxf(s[nt][0], s[nt][1]));
            rm1 = fmaxf(rm1, fmaxf(s[nt][2], s[nt][3]));
        }
        rm0 = fmaxf(rm0, __shfl_xor_sync(0xffffffffu, rm0, 1));
        rm0 = fmaxf(rm0, __shfl_xor_sync(0xffffffffu, rm0, 2));
        rm1 = fmaxf(rm1, __shfl_xor_sync(0xffffffffu, rm1, 1));
        rm1 = fmaxf(rm1, __shfl_xor_sync(0xffffffffu, rm1, 2));

        float mn0 = fmaxf(m0, rm0), mn1 = fmaxf(m1, rm1);
        float al0 = __expf(m0 - mn0), al1 = __expf(m1 - mn1);
        l0 *= al0; l1 *= al1;
        #pragma unroll
        for (int nt = 0; nt < 8; nt++) {
            o[nt][0] *= al0; o[nt][1] *= al0;
            o[nt][2] *= al1; o[nt][3] *= al1;
        }
        uint32_t* P0 = smu + PS_OFF + row_l0 * WS;
        uint32_t* P1 = smu + PS_OFF + (row_l0 + 8) * WS;
        #pragma unroll
        for (int nt = 0; nt < 8; nt++) {
            float p0 = __expf(s[nt][0] - mn0), p1 = __expf(s[nt][1] - mn0);
            float p2 = __expf(s[nt][2] - mn1), p3 = __expf(s[nt][3] - mn1);
            l0 += p0 + p1; l1 += p2 + p3;
            P0[nt * 4 + tig] = packh2(p0, p1);
            P1[nt * 4 + tig] = packh2(p2, p3);
        }
        m0 = mn0; m1 = mn1;
        __syncwarp();                 // P is warp-private

        // ---- PV: O += P @ V (4 k16 steps, B from Vt) ----
        #pragma unroll
        for (int ks = 0; ks < 4; ks++) {
            const int kb = ks * 8 + tig;
            uint32_t a0 = smu[PS_OFF + row_l0 * WS + kb];
            uint32_t a1 = smu[PS_OFF + (row_l0 + 8) * WS + kb];
            uint32_t a2 = smu[PS_OFF + row_l0 * WS + kb + 4];
            uint32_t a3 = smu[PS_OFF + (row_l0 + 8) * WS + kb + 4];
            uint32_t bb[8][2];
            #pragma unroll
            for (int nt = 0; nt < 8; nt++) {
                int n = nt * 8 + g;                  // d column
                bb[nt][0] = smu[VT_OFF + n * WS + kb];
                bb[nt][1] = smu[VT_OFF + n * WS + kb + 4];
            }
            #pragma unroll
            for (int nt = 0; nt < 8; nt++)
                mma_f16(o[nt], a0, a1, a2, a3, bb[nt][0], bb[nt][1]);
        }
        __syncthreads();              // PV done before next tile overwrite
    }

    l0 += __shfl_xor_sync(0xffffffffu, l0, 1);
    l0 += __shfl_xor_sync(0xffffffffu, l0, 2);
    l1 += __shfl_xor_sync(0xffffffffu, l1, 1);
    l1 += __shfl_xor_sync(0xffffffffu, l1, 2);

    // tail: rare global tokens beyond kend (Q pre-scaled -> no extra 1/8)
    const int ng = g_gcnt[b];
    for (int gi = 0; gi < ng; gi++) {
        int k = g_glist[b * T_ + gi];
        if (k < kend) continue;
        const __half* Kr = Kg + (size_t)k * HD;
        const __half* Vr = Vg + (size_t)k * HD;
        const __half* q0p = Qg + (size_t)row_q0 * HD;
        const __half* q1p = Qg + (size_t)row_q1 * HD;
        float s0 = 0.f, s1 = 0.f;
        #pragma unroll
        for (int d = 0; d < HD; d++) {
            float kv = __half2float(Kr[d]);
            s0 = fmaf(__half2float(q0p[d]), kv, s0);
            s1 = fmaf(__half2float(q1p[d]), kv, s1);
        }
        float mn0 = fmaxf(m0, s0), mn1 = fmaxf(m1, s1);
        float al0 = __expf(m0 - mn0), al1 = __expf(m1 - mn1);
        float p0 = __expf(s0 - mn0), p1 = __expf(s1 - mn1);
        l0 = l0 * al0 + p0; l1 = l1 * al1 + p1;
        m0 = mn0; m1 = mn1;
        #pragma unroll
        for (int nt = 0; nt < 8; nt++) {
            int cc = nt * 8 + 2 * tig;
            float v0 = __half2float(Vr[cc]), v1 = __half2float(Vr[cc + 1]);
            o[nt][0] = o[nt][0] * al0 + p0 * v0;
            o[nt][1] = o[nt][1] * al0 + p0 * v1;
            o[nt][2] = o[nt][2] * al1 + p1 * v0;
            o[nt][3] = o[nt][3] * al1 + p1 * v1;
        }
    }

    float i0 = 1.f / l0, i1 = 1.f / l1;
    float* O0 = g_att + ((size_t)(b * T_ + row_q0)) * HID + h * HD;
    float* O1 = g_att + ((size_t)(b * T_ + row_q1)) * HID + h * HD;
    #pragma unroll
    for (int nt = 0; nt < 8; nt++) {
        int cc = nt * 8 + 2 * tig;
        float2 v0 = { o[nt][0] * i0, o[nt][1] * i0 };
        float2 v1 = { o[nt][2] * i1, o[nt][3] * i1 };
        *(float2*)(O0 + cc) = v0;
        *(float2*)(O1 + cc) = v1;
    }
}

// ---------------- launch -----------------------------------------------------
extern "C" void kernel_launch(void* const* d_in, const int* in_sizes, int n_in,
                              void* d_out, int out_size)
{
    (void)in_sizes; (void)n_in; (void)out_size;
    const float* x      = (const float*)d_in[0];
    const int*   ids    = (const int*)d_in[1];
    const float* qkv_w  = (const float*)d_in[2];
    const float* qkv_b  = (const float*)d_in[3];
    const float* out_w  = (const float*)d_in[4];
    const float* out_b  = (const float*)d_in[5];
    float*       out    = (float*)d_out;

    float* p_att = nullptr;
    cudaGetSymbolAddress((void**)&p_att, g_att);

    cudaFuncSetAttribute(gemm_f16<0>,
                         cudaFuncAttributeMaxDynamicSharedMemorySize, GS_TOTAL);
    cudaFuncSetAttribute(gemm_f16<1>,
                         cudaFuncAttributeMaxDynamicSharedMemorySize, GS_TOTAL);
    cudaFuncSetAttribute(attn_f16,
                         cudaFuncAttributeMaxDynamicSharedMemorySize, AT_BYTES);

    // 1. cos/sin table
    costab_kernel<<<T_ * 32 / 256, 256>>>();
    // 2-3. global-token mask
    ginit_kernel<<<1, 32>>>();
    gmask_kernel<<<(B_ * T_ + 255) / 256, 256>>>(ids);
    // 4. fused qkv GEMM + bias + RoPE + split -> g_Qh/g_Kh/g_Vh (fp16)
    gemm_f16<1><<<dim3(3 * HID / 128, (B_ * T_) / 128), 256, GS_TOTAL>>>(
        x, qkv_w, qkv_b, nullptr, 3 * HID, HID);
    // 5. attention (fp16 mma flash attention)
    attn_f16<<<dim3(T_ / 128, NH, B_), 256, AT_BYTES>>>();
    // 6. out = att @ out_w^T + out_b (fp32 out)
    gemm_f16<0><<<dim3(HID / 128, (B_ * T_) / 128), 256, GS_TOTAL>>>(
        p_att, out_w, out_b, out, HID, HID);
}